// round 2
// baseline (speedup 1.0000x reference)
#include <cuda_runtime.h>
#include <cuda_bf16.h>

// ---------------------------------------------------------------------------
// GraphEncoder: 3-layer GAT (H=4 heads, C=128 per head, HID=128), mean-pool.
// edge_index / batch are int32 (JAX x64 disabled downgrades int64 -> int32).
// ---------------------------------------------------------------------------

#define NF    5
#define HID   128
#define NH    4
#define CC    128          // per-head channel dim
#define HC    512          // NH * CC
#define NL    3
#define NB    32

#define MAXN  10240
#define MAXE  163840
#define MAXET (MAXE + MAXN)

// ------------------------- static device scratch ---------------------------
__device__ float    g_h[2][MAXN * HID];      // ping-pong node features
__device__ float    g_hW[MAXN * HC];         // h @ W
__device__ float    g_asrc[MAXN * NH];
__device__ float    g_adst[MAXN * NH];
__device__ unsigned g_m[MAXN * NH];          // segment max (ordered-uint encoding)
__device__ float    g_denom[MAXN * NH];
__device__ float    g_acc[MAXN * HC];        // unnormalized message accumulator
__device__ float    g_e[MAXET * NH];         // leakyrelu'd logits per edge
__device__ float    g_pool[NB * HID];
__device__ int      g_cnt[NB];

// ------------------------- helpers -----------------------------------------
__device__ __forceinline__ unsigned fenc(float f) {
    unsigned u = __float_as_uint(f);
    return (u & 0x80000000u) ? ~u : (u | 0x80000000u);
}
__device__ __forceinline__ float fdec(unsigned v) {
    return __uint_as_float((v & 0x80000000u) ? (v ^ 0x80000000u) : ~v);
}

// ------------------------- kernels ------------------------------------------

// h0 = relu(x @ node_W + node_b)
__global__ void k_node_enc(const float* __restrict__ x,
                           const float* __restrict__ nW,
                           const float* __restrict__ nb, int N) {
    int idx = blockIdx.x * blockDim.x + threadIdx.x;
    int n = idx >> 7;            // /128
    int j = idx & 127;
    if (n >= N) return;
    float s = nb[j];
#pragma unroll
    for (int f = 0; f < NF; f++) s += x[n * NF + f] * nW[f * HID + j];
    g_h[0][n * HID + j] = fmaxf(s, 0.0f);
}

__global__ void k_zero_pool() {
    int i = blockIdx.x * blockDim.x + threadIdx.x;
    if (i < NB * HID) g_pool[i] = 0.0f;
    if (i < NB) g_cnt[i] = 0;
}

__global__ void k_zero_layer(int N) {
    int i = blockIdx.x * blockDim.x + threadIdx.x;
    if (i < N * HC) g_acc[i] = 0.0f;
    if (i < N * NH) { g_denom[i] = 0.0f; g_m[i] = 0u; }
}

// hW = h @ W : [N,128] x [128,512]. Tile 64x128, 256 threads, 8x4 microtile.
__global__ __launch_bounds__(256) void k_gemm(int cur, const float* __restrict__ W, int N) {
    __shared__ float  hs[64][HID];        // 32 KB
    __shared__ float4 ws4[32][32];        // 16 KB  (32 k-rows x 128 cols)
    const float* __restrict__ h = g_h[cur];
    int row0 = blockIdx.x * 64;
    int cb   = blockIdx.y * 128;
    int tid  = threadIdx.x;

    // load h tile (zero-pad beyond N)
    for (int i = tid; i < 64 * (HID / 4); i += 256) {
        int r  = i >> 5;        // /32 float4 per row
        int c4 = i & 31;
        float4 v = make_float4(0.f, 0.f, 0.f, 0.f);
        int gr = row0 + r;
        if (gr < N) v = *(const float4*)&h[gr * HID + c4 * 4];
        *(float4*)&hs[r][c4 * 4] = v;
    }

    int tm = tid >> 5;   // 0..7 (row group)
    int tn = tid & 31;   // 0..31 (col group of 4)
    float acc[8][4];
#pragma unroll
    for (int i = 0; i < 8; i++)
#pragma unroll
        for (int j = 0; j < 4; j++) acc[i][j] = 0.0f;

    for (int kk = 0; kk < HID; kk += 32) {
        __syncthreads();
        for (int i = tid; i < 32 * 32; i += 256) {
            int r = i >> 5, c4 = i & 31;
            ws4[r][c4] = *(const float4*)&W[(kk + r) * HC + cb + c4 * 4];
        }
        __syncthreads();
#pragma unroll
        for (int k = 0; k < 32; k++) {
            float4 b4 = ws4[k][tn];
#pragma unroll
            for (int i = 0; i < 8; i++) {
                float a = hs[tm * 8 + i][kk + k];
                acc[i][0] += a * b4.x;
                acc[i][1] += a * b4.y;
                acc[i][2] += a * b4.z;
                acc[i][3] += a * b4.w;
            }
        }
    }
#pragma unroll
    for (int i = 0; i < 8; i++) {
        int gr = row0 + tm * 8 + i;
        if (gr < N) {
            float4 v = make_float4(acc[i][0], acc[i][1], acc[i][2], acc[i][3]);
            *(float4*)&g_hW[gr * HC + cb + tn * 4] = v;
        }
    }
}

// a_src[n,h], a_dst[n,h] dot products; one block per node, warp per head.
__global__ void k_att(const float* __restrict__ asv,
                      const float* __restrict__ adv, int N) {
    int n = blockIdx.x;
    if (n >= N) return;
    int lane = threadIdx.x & 31;
    int w    = threadIdx.x >> 5;      // head
    float s1 = 0.f, s2 = 0.f;
#pragma unroll
    for (int i = 0; i < 4; i++) {
        int c = lane + i * 32;
        float v = g_hW[n * HC + w * CC + c];
        s1 += v * asv[w * CC + c];
        s2 += v * adv[w * CC + c];
    }
#pragma unroll
    for (int o = 16; o; o >>= 1) {
        s1 += __shfl_down_sync(0xffffffffu, s1, o);
        s2 += __shfl_down_sync(0xffffffffu, s2, o);
    }
    if (lane == 0) {
        g_asrc[n * NH + w] = s1;
        g_adst[n * NH + w] = s2;
    }
}

// pass 1 over edges: logits + segment max (self loops appended implicitly)
__global__ void k_edge_max(const int* __restrict__ ei, int E, int Et) {
    int e = blockIdx.x * blockDim.x + threadIdx.x;
    if (e >= Et) return;
    int src, dst;
    if (e < E) { src = ei[e]; dst = ei[E + e]; }
    else       { src = dst = e - E; }
    float4 as = *(const float4*)&g_asrc[src * NH];
    float4 ad = *(const float4*)&g_adst[dst * NH];
    float v[4] = { as.x + ad.x, as.y + ad.y, as.z + ad.z, as.w + ad.w };
#pragma unroll
    for (int h = 0; h < NH; h++) {
        float t = v[h] > 0.f ? v[h] : 0.2f * v[h];
        g_e[e * NH + h] = t;
        atomicMax(&g_m[dst * NH + h], fenc(t));
    }
}

// pass 2: ex = exp(e - m[dst]); denom += ex; acc[dst] += ex * hW[src]
// 256 threads -> 2 edges per block; 128 threads per edge (warp = head).
__global__ __launch_bounds__(256) void k_edge_agg(const int* __restrict__ ei,
                                                  int E, int Et) {
    int eidx = blockIdx.x * 2 + (threadIdx.x >> 7);
    if (eidx >= Et) return;
    int t = threadIdx.x & 127;
    int h = t >> 5;
    int src, dst;
    if (eidx < E) { src = ei[eidx]; dst = ei[E + eidx]; }
    else          { src = dst = eidx - E; }
    float ev = g_e[eidx * NH + h];
    float mv = fdec(g_m[dst * NH + h]);
    float ex = __expf(ev - mv);
    if ((t & 31) == 0) atomicAdd(&g_denom[dst * NH + h], ex);
    float4 v = *(const float4*)&g_hW[src * HC + t * 4];
    float* p = &g_acc[dst * HC + t * 4];
    atomicAdd(p + 0, v.x * ex);
    atomicAdd(p + 1, v.y * ex);
    atomicAdd(p + 2, v.z * ex);
    atomicAdd(p + 3, v.w * ex);
}

// node epilogue: normalize, head-mean, +bias, LayerNorm, relu + residual.
__global__ void k_node_fin(int cur,
                           const float* __restrict__ bias,
                           const float* __restrict__ lng,
                           const float* __restrict__ lnb,
                           float* __restrict__ out_h,
                           const int* __restrict__ batch,
                           int N, int last) {
    int n = blockIdx.x;
    if (n >= N) return;
    int j = threadIdx.x;
    float4 dn = *(const float4*)&g_denom[n * NH];
    float rd0 = 1.0f / (dn.x + 1e-16f);
    float rd1 = 1.0f / (dn.y + 1e-16f);
    float rd2 = 1.0f / (dn.z + 1e-16f);
    float rd3 = 1.0f / (dn.w + 1e-16f);
    const float* a = &g_acc[n * HC];
    float s = a[0 * CC + j] * rd0 + a[1 * CC + j] * rd1 +
              a[2 * CC + j] * rd2 + a[3 * CC + j] * rd3;
    float t = s * 0.25f + bias[j];

    // block LayerNorm over 128 lanes
    float s1 = t, s2 = t * t;
#pragma unroll
    for (int o = 16; o; o >>= 1) {
        s1 += __shfl_down_sync(0xffffffffu, s1, o);
        s2 += __shfl_down_sync(0xffffffffu, s2, o);
    }
    __shared__ float sA[4], sB[4];
    int lane = j & 31, w = j >> 5;
    if (lane == 0) { sA[w] = s1; sB[w] = s2; }
    __syncthreads();
    float S1 = sA[0] + sA[1] + sA[2] + sA[3];
    float S2 = sB[0] + sB[1] + sB[2] + sB[3];
    float mu  = S1 * (1.0f / HID);
    float var = fmaxf(S2 * (1.0f / HID) - mu * mu, 0.0f);
    float y = (t - mu) * rsqrtf(var + 1e-5f) * lng[j] + lnb[j];
    float hp = g_h[cur][n * HID + j];
    float hn = fmaxf(y, 0.0f) + hp;
    g_h[cur ^ 1][n * HID + j] = hn;
    if (last) {
        out_h[n * HID + j] = hn;
        int b = batch[n];
        atomicAdd(&g_pool[b * HID + j], hn);
        if (j == 0) atomicAdd(&g_cnt[b], 1);
    }
}

__global__ void k_pool_out(float* __restrict__ o) {
    int b = blockIdx.x, j = threadIdx.x;
    float c = (float)g_cnt[b];
    o[b * HID + j] = g_pool[b * HID + j] / fmaxf(c, 1.0f);
}

// ------------------------- host entry ---------------------------------------
extern "C" void kernel_launch(void* const* d_in, const int* in_sizes, int n_in,
                              void* d_out, int out_size) {
    const float* x      = (const float*)d_in[0];
    const int*   ei     = (const int*)d_in[1];
    const int*   batch  = (const int*)d_in[2];
    const float* node_W = (const float*)d_in[3];
    const float* node_b = (const float*)d_in[4];
    const float* Ws     = (const float*)d_in[5];
    const float* att_s  = (const float*)d_in[6];
    const float* att_d  = (const float*)d_in[7];
    const float* biases = (const float*)d_in[8];
    const float* ln_g   = (const float*)d_in[9];
    const float* ln_b   = (const float*)d_in[10];

    int N  = in_sizes[0] / NF;
    int E  = in_sizes[1] / 2;
    int Et = E + N;
    float* out = (float*)d_out;

    k_node_enc<<<(N * HID + 255) / 256, 256>>>(x, node_W, node_b, N);
    k_zero_pool<<<(NB * HID + 255) / 256, 256>>>();

    int cur = 0;
    for (int l = 0; l < NL; l++) {
        k_zero_layer<<<(N * HC + 255) / 256, 256>>>(N);
        k_gemm<<<dim3((N + 63) / 64, 4), 256>>>(cur, Ws + (size_t)l * HID * HC, N);
        k_att<<<N, 128>>>(att_s + (size_t)l * NH * CC, att_d + (size_t)l * NH * CC, N);
        k_edge_max<<<(Et + 255) / 256, 256>>>(ei, E, Et);
        k_edge_agg<<<(Et + 1) / 2, 256>>>(ei, E, Et);
        k_node_fin<<<N, 128>>>(cur, biases + (size_t)l * HID,
                               ln_g + (size_t)l * HID, ln_b + (size_t)l * HID,
                               out, batch, N, (l == NL - 1) ? 1 : 0);
        cur ^= 1;
    }
    k_pool_out<<<NB, HID>>>(out + (size_t)N * HID);
}

// round 3
// speedup vs baseline: 4.8443x; 4.8443x over previous
#include <cuda_runtime.h>
#include <cuda_bf16.h>

// ---------------------------------------------------------------------------
// GraphEncoder: 3-layer GAT (H=4, C=128, HID=128), mean-pool. CSR-based:
//   build CSR by dst once, then per layer one fused kernel does
//   max -> exp/denom/weighted-gather (registers) -> head-mean -> LN ->
//   relu+residual -> (last layer) pool. No atomics in the hot path.
// ---------------------------------------------------------------------------

#define NF    5
#define HID   128
#define NH    4
#define CC    128
#define HC    512          // NH * CC
#define NL    3
#define NB    32

#define MAXN  10240
#define MAXE  163840
#define MAXET (MAXE + MAXN)
#define CH    256          // src-index smem chunk

// ------------------------- static device scratch ---------------------------
__device__ float g_h[2][MAXN * HID];
__device__ float g_hW[MAXN * HC];
__device__ float g_asrc[MAXN * NH];
__device__ float g_adst[MAXN * NH];
__device__ int   g_deg[MAXN];
__device__ int   g_off[MAXN + 1];
__device__ int   g_cur[MAXN];
__device__ int   g_csr[MAXET];
__device__ float g_pool[NB * HID];
__device__ int   g_cnt[NB];

// ------------------------- CSR build ----------------------------------------
__global__ void k_zero_deg(int N) {
    int i = blockIdx.x * blockDim.x + threadIdx.x;
    if (i < N) g_deg[i] = 0;
}

__global__ void k_deg(const int* __restrict__ ei, int E, int Et) {
    int e = blockIdx.x * blockDim.x + threadIdx.x;
    if (e >= Et) return;
    int dst = (e < E) ? ei[E + e] : (e - E);
    atomicAdd(&g_deg[dst], 1);
}

// single-block exclusive scan of g_deg -> g_off (and g_cur copy). N <= 16384.
__global__ __launch_bounds__(1024) void k_scan(int N) {
    __shared__ int sp[1024];
    const int IT = 16;
    int tid  = threadIdx.x;
    int base = tid * IT;
    int loc[IT];
    int s = 0;
#pragma unroll
    for (int i = 0; i < IT; i++) {
        int idx = base + i;
        int v = (idx < N) ? g_deg[idx] : 0;
        loc[i] = s;
        s += v;
    }
    sp[tid] = s;
    __syncthreads();
    for (int st = 1; st < 1024; st <<= 1) {
        int v = (tid >= st) ? sp[tid - st] : 0;
        __syncthreads();
        sp[tid] += v;
        __syncthreads();
    }
    int ex = sp[tid] - s;
#pragma unroll
    for (int i = 0; i < IT; i++) {
        int idx = base + i;
        if (idx <= N) {
            int o = ex + loc[i];
            g_off[idx] = o;
            if (idx < N) g_cur[idx] = o;
        }
    }
}

__global__ void k_scatter(const int* __restrict__ ei, int E, int Et) {
    int e = blockIdx.x * blockDim.x + threadIdx.x;
    if (e >= Et) return;
    int src, dst;
    if (e < E) { src = ei[e]; dst = ei[E + e]; }
    else       { src = dst = e - E; }
    int pos = atomicAdd(&g_cur[dst], 1);
    g_csr[pos] = src;
}

// ------------------------- misc ----------------------------------------------
__global__ void k_node_enc(const float* __restrict__ x,
                           const float* __restrict__ nW,
                           const float* __restrict__ nb, int N) {
    int idx = blockIdx.x * blockDim.x + threadIdx.x;
    int n = idx >> 7;
    int j = idx & 127;
    if (n >= N) return;
    float s = nb[j];
#pragma unroll
    for (int f = 0; f < NF; f++) s += x[n * NF + f] * nW[f * HID + j];
    g_h[0][n * HID + j] = fmaxf(s, 0.0f);
}

__global__ void k_zero_pool() {
    int i = blockIdx.x * blockDim.x + threadIdx.x;
    if (i < NB * HID) g_pool[i] = 0.0f;
    if (i < NB) g_cnt[i] = 0;
}

// ------------------------- GEMM + fused attention dots ----------------------
// hW = h @ W : [N,128]x[128,512], tile 64x128 (blockIdx.y = head).
// Epilogue computes a_src/a_dst per (row, head) via intra-warp reduce.
__global__ __launch_bounds__(256) void k_gemm(int cur, const float* __restrict__ W,
                                              const float* __restrict__ attS,
                                              const float* __restrict__ attD, int N) {
    __shared__ float  hs[64][HID];
    __shared__ float4 ws4[32][32];
    const float* __restrict__ h = g_h[cur];
    int row0 = blockIdx.x * 64;
    int cb   = blockIdx.y * 128;         // head * CC
    int tid  = threadIdx.x;

    for (int i = tid; i < 64 * (HID / 4); i += 256) {
        int r = i >> 5, c4 = i & 31;
        float4 v = make_float4(0.f, 0.f, 0.f, 0.f);
        int gr = row0 + r;
        if (gr < N) v = *(const float4*)&h[gr * HID + c4 * 4];
        *(float4*)&hs[r][c4 * 4] = v;
    }

    int tm = tid >> 5;     // warp id = row group (warp-uniform)
    int tn = tid & 31;
    float acc[8][4];
#pragma unroll
    for (int i = 0; i < 8; i++)
#pragma unroll
        for (int j = 0; j < 4; j++) acc[i][j] = 0.0f;

    for (int kk = 0; kk < HID; kk += 32) {
        __syncthreads();
        for (int i = tid; i < 32 * 32; i += 256) {
            int r = i >> 5, c4 = i & 31;
            ws4[r][c4] = *(const float4*)&W[(kk + r) * HC + cb + c4 * 4];
        }
        __syncthreads();
#pragma unroll
        for (int k = 0; k < 32; k++) {
            float4 b4 = ws4[k][tn];
#pragma unroll
            for (int i = 0; i < 8; i++) {
                float a = hs[tm * 8 + i][kk + k];
                acc[i][0] += a * b4.x;
                acc[i][1] += a * b4.y;
                acc[i][2] += a * b4.z;
                acc[i][3] += a * b4.w;
            }
        }
    }

    float s4[4], d4[4];
#pragma unroll
    for (int j = 0; j < 4; j++) {
        s4[j] = attS[cb + tn * 4 + j];
        d4[j] = attD[cb + tn * 4 + j];
    }
#pragma unroll
    for (int i = 0; i < 8; i++) {
        int gr = row0 + tm * 8 + i;
        float sv = 0.f, dv = 0.f;
#pragma unroll
        for (int j = 0; j < 4; j++) {
            sv += acc[i][j] * s4[j];
            dv += acc[i][j] * d4[j];
        }
#pragma unroll
        for (int o = 16; o; o >>= 1) {
            sv += __shfl_down_sync(0xffffffffu, sv, o);
            dv += __shfl_down_sync(0xffffffffu, dv, o);
        }
        if (gr < N) {
            float4 v = make_float4(acc[i][0], acc[i][1], acc[i][2], acc[i][3]);
            *(float4*)&g_hW[gr * HC + cb + tn * 4] = v;
            if (tn == 0) {
                g_asrc[gr * NH + blockIdx.y] = sv;
                g_adst[gr * NH + blockIdx.y] = dv;
            }
        }
    }
}

// ------------------------- fused per-node layer kernel -----------------------
// Block = one dst node. Warp w = head w. Thread t owns channels 4t..4t+3.
__global__ __launch_bounds__(128) void k_layer(int cur,
                                               const float* __restrict__ bias,
                                               const float* __restrict__ lng,
                                               const float* __restrict__ lnb,
                                               float* __restrict__ out_h,
                                               const int* __restrict__ batch,
                                               int N, int last) {
    int n = blockIdx.x;
    if (n >= N) return;
    int tid  = threadIdx.x;
    int lane = tid & 31;
    int w    = tid >> 5;               // head
    int off0 = g_off[n];
    int deg  = g_off[n + 1] - off0;

    __shared__ int   s_src[CH];
    __shared__ float s_acc[HC];

    float ad = g_adst[n * NH + w];

    // Phase 1: per-head max over incident edges
    float m = -1e30f;
    for (int i = lane; i < deg; i += 32) {
        int s = g_csr[off0 + i];
        float e = g_asrc[s * NH + w] + ad;
        e = e > 0.f ? e : 0.2f * e;
        m = fmaxf(m, e);
    }
#pragma unroll
    for (int o = 16; o; o >>= 1) m = fmaxf(m, __shfl_xor_sync(0xffffffffu, m, o));

    // Phase 2: exp weights, denominator, weighted gather of hW[src]
    float a0 = 0.f, a1 = 0.f, a2 = 0.f, a3 = 0.f, den = 0.f;
    for (int c0 = 0; c0 < deg; c0 += CH) {
        int len = min(CH, deg - c0);
        __syncthreads();
        for (int i = tid; i < len; i += 128) s_src[i] = g_csr[off0 + c0 + i];
        __syncthreads();
#pragma unroll 4
        for (int i = 0; i < len; i++) {
            int s = s_src[i];
            float e = g_asrc[s * NH + w] + ad;     // warp-broadcast load
            e = e > 0.f ? e : 0.2f * e;
            float ex = __expf(e - m);
            den += ex;
            float4 v = *(const float4*)&g_hW[s * HC + tid * 4];
            a0 += v.x * ex; a1 += v.y * ex; a2 += v.z * ex; a3 += v.w * ex;
        }
    }
    float rd = 1.0f / (den + 1e-16f);
    s_acc[tid * 4 + 0] = a0 * rd;
    s_acc[tid * 4 + 1] = a1 * rd;
    s_acc[tid * 4 + 2] = a2 * rd;
    s_acc[tid * 4 + 3] = a3 * rd;
    __syncthreads();

    // head mean + bias
    int j = tid;
    float t = 0.25f * (s_acc[j] + s_acc[128 + j] + s_acc[256 + j] + s_acc[384 + j])
            + bias[j];

    // LayerNorm over 128 channels
    float s1 = t, s2 = t * t;
#pragma unroll
    for (int o = 16; o; o >>= 1) {
        s1 += __shfl_down_sync(0xffffffffu, s1, o);
        s2 += __shfl_down_sync(0xffffffffu, s2, o);
    }
    __shared__ float sA[4], sB[4];
    if (lane == 0) { sA[w] = s1; sB[w] = s2; }
    __syncthreads();
    float S1 = sA[0] + sA[1] + sA[2] + sA[3];
    float S2 = sB[0] + sB[1] + sB[2] + sB[3];
    float mu  = S1 * (1.0f / HID);
    float var = fmaxf(S2 * (1.0f / HID) - mu * mu, 0.0f);
    float y = (t - mu) * rsqrtf(var + 1e-5f) * lng[j] + lnb[j];
    float hp = g_h[cur][n * HID + j];
    float hn = fmaxf(y, 0.0f) + hp;
    g_h[cur ^ 1][n * HID + j] = hn;
    if (last) {
        out_h[n * HID + j] = hn;
        int b = batch[n];
        atomicAdd(&g_pool[b * HID + j], hn);
        if (j == 0) atomicAdd(&g_cnt[b], 1);
    }
}

__global__ void k_pool_out(float* __restrict__ o) {
    int b = blockIdx.x, j = threadIdx.x;
    float c = (float)g_cnt[b];
    o[b * HID + j] = g_pool[b * HID + j] / fmaxf(c, 1.0f);
}

// ------------------------- host entry ---------------------------------------
extern "C" void kernel_launch(void* const* d_in, const int* in_sizes, int n_in,
                              void* d_out, int out_size) {
    const float* x      = (const float*)d_in[0];
    const int*   ei     = (const int*)d_in[1];
    const int*   batch  = (const int*)d_in[2];
    const float* node_W = (const float*)d_in[3];
    const float* node_b = (const float*)d_in[4];
    const float* Ws     = (const float*)d_in[5];
    const float* att_s  = (const float*)d_in[6];
    const float* att_d  = (const float*)d_in[7];
    const float* biases = (const float*)d_in[8];
    const float* ln_g   = (const float*)d_in[9];
    const float* ln_b   = (const float*)d_in[10];

    int N  = in_sizes[0] / NF;
    int E  = in_sizes[1] / 2;
    int Et = E + N;
    float* out = (float*)d_out;

    // CSR build (once, reused by all layers)
    k_zero_deg<<<(N + 255) / 256, 256>>>(N);
    k_deg<<<(Et + 255) / 256, 256>>>(ei, E, Et);
    k_scan<<<1, 1024>>>(N);
    k_scatter<<<(Et + 255) / 256, 256>>>(ei, E, Et);

    k_node_enc<<<(N * HID + 255) / 256, 256>>>(x, node_W, node_b, N);
    k_zero_pool<<<(NB * HID + 255) / 256, 256>>>();

    int cur = 0;
    for (int l = 0; l < NL; l++) {
        k_gemm<<<dim3((N + 63) / 64, 4), 256>>>(cur, Ws + (size_t)l * HID * HC,
                                                att_s + (size_t)l * NH * CC,
                                                att_d + (size_t)l * NH * CC, N);
        k_layer<<<N, 128>>>(cur, biases + (size_t)l * HID,
                            ln_g + (size_t)l * HID, ln_b + (size_t)l * HID,
                            out, batch, N, (l == NL - 1) ? 1 : 0);
        cur ^= 1;
    }
    k_pool_out<<<NB, HID>>>(out + (size_t)N * HID);
}